// round 3
// baseline (speedup 1.0000x reference)
#include <cuda_runtime.h>
#include <cuda_bf16.h>
#include <cstdint>

#define M_DIM 512
#define K_DIM 8192
#define N_DIM 8192
#define FPN   256
#define INTN  7936   // = 124 * 64

// ---------------- scratch (no allocations allowed) ----------------
__device__ __align__(128) int8_t g_qs[(size_t)M_DIM * INTN]; // quantized activations (q_s)
__device__ __align__(128) int8_t g_w8[(size_t)N_DIM * INTN]; // repacked int8 weights (65 MB)
__device__ __align__(128) float  g_fpx[M_DIM * FPN];         // gathered fp activations
__device__ float  g_srow[M_DIM];                             // per-row scale
__device__ float  g_off[M_DIM];                              // row_min + 8*scale

// resolved pointers / modes
__device__ const float* g_p_bias;
__device__ const float* g_p_ws;
__device__ const float* g_p_rw;
__device__ int          g_wmode;   // 0 = int8 passthrough, 1 = int32, 2 = bf16
__device__ const int8_t* g_p_w8;   // B pointer used by the GEMM

// ---------------- K-1: detect w_int's real dtype ----------------
// int32 array of values in [-8,7]: every aligned int32 read is in [-8,7].
// Random int8 bytes or bf16 bit patterns cannot satisfy that for 4096 reads.
// bf16 array of ints in [-8,7]: every bf16 converts to an exact integer in range.
__global__ void detect_w_kernel(const void* wraw)
{
    __shared__ int s_i32_bad, s_bf16_bad;
    if (threadIdx.x == 0) { s_i32_bad = 0; s_bf16_bad = 0; }
    __syncthreads();

    const int32_t* wi = (const int32_t*)wraw;
    for (int i = threadIdx.x; i < 4096; i += 256) {
        int32_t v = wi[i];
        if (v < -8 || v > 7) s_i32_bad = 1;
    }
    const __nv_bfloat16* wb = (const __nv_bfloat16*)wraw;
    for (int i = threadIdx.x; i < 4096; i += 256) {
        float f = __bfloat162float(wb[i]);
        if (!(f >= -8.0f && f <= 7.0f) || f != rintf(f)) s_bf16_bad = 1;
    }
    __syncthreads();
    if (threadIdx.x == 0) {
        if (!s_i32_bad)       { g_wmode = 1; g_p_w8 = g_w8; }
        else if (!s_bf16_bad) { g_wmode = 2; g_p_w8 = g_w8; }
        else                  { g_wmode = 0; g_p_w8 = (const int8_t*)wraw; }
    }
}

// ---------------- K-2: repack weights to int8 if needed ----------------
__global__ __launch_bounds__(256) void repack_w_kernel(const void* wraw)
{
    const int mode = g_wmode;
    if (mode == 0) return;
    const size_t total = (size_t)N_DIM * INTN;
    const size_t idx0 = ((size_t)blockIdx.x * 256 + threadIdx.x) * 16;
    if (idx0 >= total) return;

    int8_t outv[16];
    if (mode == 1) {
        const int4* wi = (const int4*)wraw;   // 4 int32 per int4
        #pragma unroll
        for (int j = 0; j < 4; j++) {
            int4 v = wi[idx0 / 4 + j];
            outv[j * 4 + 0] = (int8_t)v.x;
            outv[j * 4 + 1] = (int8_t)v.y;
            outv[j * 4 + 2] = (int8_t)v.z;
            outv[j * 4 + 3] = (int8_t)v.w;
        }
    } else {
        const __nv_bfloat16* wb = (const __nv_bfloat16*)wraw;
        #pragma unroll
        for (int j = 0; j < 16; j++)
            outv[j] = (int8_t)(int)__bfloat162float(wb[idx0 + j]);
    }
    *(int4*)(g_w8 + idx0) = *(int4*)outv;
}

// ---------------- K0: classify the three 8192-float arrays ----------------
// weights_scales: all values in (0.005, 0.015)  -> min > 0
// bias:           N(0, 0.01)                    -> amax < 0.1
// reduced_w:      ws * sum(w_int) (std ~4)      -> amax >> 0.1
__global__ void classify_kernel(const float* c0, const float* c1, const float* c2)
{
    const float* cand[3] = {c0, c1, c2};
    __shared__ float red[64];
    __shared__ float mins[3], maxs[3];
    for (int a = 0; a < 3; a++) {
        float mn = 3.4e38f, mx = -3.4e38f;
        for (int i = threadIdx.x; i < 8192; i += 256) {
            float v = cand[a][i];
            mn = fminf(mn, v); mx = fmaxf(mx, v);
        }
        #pragma unroll
        for (int o = 16; o > 0; o >>= 1) {
            mn = fminf(mn, __shfl_xor_sync(0xFFFFFFFFu, mn, o));
            mx = fmaxf(mx, __shfl_xor_sync(0xFFFFFFFFu, mx, o));
        }
        int wid = threadIdx.x >> 5;
        if ((threadIdx.x & 31) == 0) { red[wid] = mn; red[32 + wid] = mx; }
        __syncthreads();
        if (threadIdx.x == 0) {
            float m1 = red[0], m2 = red[32];
            #pragma unroll
            for (int i = 1; i < 8; i++) { m1 = fminf(m1, red[i]); m2 = fmaxf(m2, red[32 + i]); }
            mins[a] = m1; maxs[a] = m2;
        }
        __syncthreads();
    }
    if (threadIdx.x == 0) {
        int iws = -1, ibias = -1, irw = -1;
        for (int a = 0; a < 3; a++) if (mins[a] > 0.0f) iws = a;
        for (int a = 0; a < 3; a++) {
            if (a == iws) continue;
            float amax = fmaxf(fabsf(mins[a]), fabsf(maxs[a]));
            if (amax < 0.1f) ibias = a;
        }
        for (int a = 0; a < 3; a++) if (a != iws && a != ibias) irw = a;
        g_p_ws   = cand[iws];
        g_p_bias = cand[ibias];
        g_p_rw   = cand[irw];
    }
}

// ---------------- K1: gather + rowwise 4-bit quantization ----------------
__global__ __launch_bounds__(256) void quant_kernel(
    const float* __restrict__ x,
    const int*   __restrict__ int_idx,
    const int*   __restrict__ fp_idx)
{
    __shared__ float s_val[INTN];   // 31744 B
    __shared__ float s_red[80];
    const int m = blockIdx.x;
    const float* xrow = x + (size_t)m * K_DIM;

    float lmin = 3.4e38f, lmax = -3.4e38f;
    for (int k = threadIdx.x; k < INTN; k += 256) {
        float v = xrow[int_idx[k]];
        s_val[k] = v;
        lmin = fminf(lmin, v);
        lmax = fmaxf(lmax, v);
    }
    #pragma unroll
    for (int o = 16; o > 0; o >>= 1) {
        lmin = fminf(lmin, __shfl_xor_sync(0xFFFFFFFFu, lmin, o));
        lmax = fmaxf(lmax, __shfl_xor_sync(0xFFFFFFFFu, lmax, o));
    }
    const int wid = threadIdx.x >> 5;
    if ((threadIdx.x & 31) == 0) { s_red[wid] = lmin; s_red[32 + wid] = lmax; }
    __syncthreads();
    if (threadIdx.x == 0) {
        float mn = s_red[0], mx = s_red[32];
        #pragma unroll
        for (int i = 1; i < 8; i++) { mn = fminf(mn, s_red[i]); mx = fmaxf(mx, s_red[32 + i]); }
        float sc = (mx - mn) / 15.0f;
        s_red[64] = mn; s_red[65] = sc;
        g_srow[m] = sc;
        g_off[m]  = mn + 8.0f * sc;
    }
    __syncthreads();
    const float mn = s_red[64], sc = s_red[65];
    for (int k = threadIdx.x; k < INTN; k += 256) {
        float q = rintf((s_val[k] - mn) / sc);   // matches jnp.round (half-to-even)
        q = fminf(fmaxf(q, 0.0f), 15.0f);
        g_qs[(size_t)m * INTN + k] = (int8_t)((int)q - 8);
    }
    for (int k = threadIdx.x; k < FPN; k += 256)
        g_fpx[m * FPN + k] = xrow[fp_idx[k]];
}

// ---------------- K2: fp path (tf32 mma) -> initializes out ----------------
__device__ __forceinline__ float to_tf32(float v) {
    uint32_t t;
    asm("cvt.rna.tf32.f32 %0, %1;" : "=r"(t) : "f"(v));
    return __uint_as_float(t);
}

__global__ __launch_bounds__(256) void fp_gemm_kernel(
    const float* __restrict__ fpw,   // [N, 256]
    float*       __restrict__ out)   // [M, N]
{
    __shared__ float s_a[128][20];
    __shared__ float s_b[128][20];
    const float* __restrict__ bias = g_p_bias;
    const float* __restrict__ rw   = g_p_rw;
    const int bm = blockIdx.y, bn = blockIdx.x;
    const int tid = threadIdx.x;
    const int wid = tid >> 5, lane = tid & 31;
    const int wm = wid & 1, wn = wid >> 1;   // warp tile: 64 x 32
    const int g = lane >> 2, tig = lane & 3;

    float acc[4][4][4];
    #pragma unroll
    for (int a = 0; a < 4; a++)
        #pragma unroll
        for (int b = 0; b < 4; b++)
            #pragma unroll
            for (int c = 0; c < 4; c++) acc[a][b][c] = 0.0f;

    for (int kt = 0; kt < FPN / 16; kt++) {
        const int k0 = kt * 16;
        for (int i = tid; i < 128 * 16; i += 256) {
            int r = i >> 4, c = i & 15;
            s_a[r][c] = to_tf32(g_fpx[(bm * 128 + r) * FPN + k0 + c]);
        }
        for (int i = tid; i < 128 * 16; i += 256) {
            int r = i >> 4, c = i & 15;
            s_b[r][c] = to_tf32(fpw[(size_t)(bn * 128 + r) * FPN + k0 + c]);
        }
        __syncthreads();
        #pragma unroll
        for (int kk = 0; kk < 16; kk += 8) {
            uint32_t afr[4][4], bfr[4][2];
            #pragma unroll
            for (int mi = 0; mi < 4; mi++) {
                int r0 = wm * 64 + mi * 16;
                afr[mi][0] = __float_as_uint(s_a[r0 + g][kk + tig]);
                afr[mi][1] = __float_as_uint(s_a[r0 + 8 + g][kk + tig]);
                afr[mi][2] = __float_as_uint(s_a[r0 + g][kk + tig + 4]);
                afr[mi][3] = __float_as_uint(s_a[r0 + 8 + g][kk + tig + 4]);
            }
            #pragma unroll
            for (int ni = 0; ni < 4; ni++) {
                int c0 = wn * 32 + ni * 8;
                bfr[ni][0] = __float_as_uint(s_b[c0 + g][kk + tig]);
                bfr[ni][1] = __float_as_uint(s_b[c0 + g][kk + tig + 4]);
            }
            #pragma unroll
            for (int mi = 0; mi < 4; mi++)
                #pragma unroll
                for (int ni = 0; ni < 4; ni++) {
                    asm volatile(
                        "mma.sync.aligned.m16n8k8.row.col.f32.tf32.tf32.f32 "
                        "{%0,%1,%2,%3}, {%4,%5,%6,%7}, {%8,%9}, {%0,%1,%2,%3};"
                        : "+f"(acc[mi][ni][0]), "+f"(acc[mi][ni][1]),
                          "+f"(acc[mi][ni][2]), "+f"(acc[mi][ni][3])
                        : "r"(afr[mi][0]), "r"(afr[mi][1]), "r"(afr[mi][2]), "r"(afr[mi][3]),
                          "r"(bfr[ni][0]), "r"(bfr[ni][1]));
                }
        }
        __syncthreads();
    }

    #pragma unroll
    for (int mi = 0; mi < 4; mi++) {
        int m0 = bm * 128 + wm * 64 + mi * 16 + g;
        float off0 = g_off[m0], off1 = g_off[m0 + 8];
        #pragma unroll
        for (int ni = 0; ni < 4; ni++) {
            int n0 = bn * 128 + wn * 32 + ni * 8 + tig * 2;
            float b0 = bias[n0], b1 = bias[n0 + 1];
            float r0 = rw[n0],   r1 = rw[n0 + 1];
            out[(size_t)m0 * N_DIM + n0]           = acc[mi][ni][0] + b0 + off0 * r0;
            out[(size_t)m0 * N_DIM + n0 + 1]       = acc[mi][ni][1] + b1 + off0 * r1;
            out[(size_t)(m0 + 8) * N_DIM + n0]     = acc[mi][ni][2] + b0 + off1 * r0;
            out[(size_t)(m0 + 8) * N_DIM + n0 + 1] = acc[mi][ni][3] + b1 + off1 * r1;
        }
    }
}

// ---------------- K3: int8 GEMM (exact), out += acc * srow[m] * ws[n] ----------------
__device__ __forceinline__ void cp_async16(void* smem_ptr, const void* gmem_ptr) {
    uint32_t s = (uint32_t)__cvta_generic_to_shared(smem_ptr);
    asm volatile("cp.async.cg.shared.global [%0], [%1], 16;\n" :: "r"(s), "l"(gmem_ptr));
}
#define CP_COMMIT() asm volatile("cp.async.commit_group;\n" ::)
#define CP_WAIT(N)  asm volatile("cp.async.wait_group %0;\n" :: "n"(N))

#define SROW 80   // padded smem row stride (bytes): conflict-free u32 frag loads

__global__ __launch_bounds__(256) void int_gemm_kernel(
    float* __restrict__ out)  // [M, N]
{
    __shared__ int8_t s_a[2][128 * SROW];
    __shared__ int8_t s_b[2][128 * SROW];
    const int8_t* __restrict__ w  = g_p_w8;   // resolved int8 weights
    const float*  __restrict__ ws = g_p_ws;
    const int bm = blockIdx.y, bn = blockIdx.x;
    const int tid = threadIdx.x;
    const int wid = tid >> 5, lane = tid & 31;
    const int wm = wid & 1, wn = wid >> 1;
    const int g = lane >> 2, tig = lane & 3;

    int acc[4][4][4];
    #pragma unroll
    for (int a = 0; a < 4; a++)
        #pragma unroll
        for (int b = 0; b < 4; b++)
            #pragma unroll
            for (int c = 0; c < 4; c++) acc[a][b][c] = 0;

    const int KT = INTN / 64;  // 124

    auto load_stage = [&](int st, int kt) {
        const int k0 = kt * 64;
        #pragma unroll
        for (int j = 0; j < 2; j++) {
            int i = tid + j * 256;
            int r = i >> 2, cs = (i & 3) * 16;
            cp_async16(&s_a[st][r * SROW + cs],
                       g_qs + (size_t)(bm * 128 + r) * INTN + k0 + cs);
        }
        #pragma unroll
        for (int j = 0; j < 2; j++) {
            int i = tid + j * 256;
            int r = i >> 2, cs = (i & 3) * 16;
            cp_async16(&s_b[st][r * SROW + cs],
                       w + (size_t)(bn * 128 + r) * INTN + k0 + cs);
        }
    };

    load_stage(0, 0);
    CP_COMMIT();

    for (int kt = 0; kt < KT; kt++) {
        if (kt + 1 < KT) {
            load_stage((kt + 1) & 1, kt + 1);
            CP_COMMIT();
            CP_WAIT(1);
        } else {
            CP_WAIT(0);
        }
        __syncthreads();

        const int8_t* sa = s_a[kt & 1];
        const int8_t* sb = s_b[kt & 1];
        #pragma unroll
        for (int kk = 0; kk < 64; kk += 32) {
            uint32_t afr[4][4], bfr[4][2];
            #pragma unroll
            for (int mi = 0; mi < 4; mi++) {
                int r0 = (wm * 64 + mi * 16 + g) * SROW;
                int r8 = r0 + 8 * SROW;
                afr[mi][0] = *(const uint32_t*)(sa + r0 + kk + 4 * tig);
                afr[mi][1] = *(const uint32_t*)(sa + r8 + kk + 4 * tig);
                afr[mi][2] = *(const uint32_t*)(sa + r0 + kk + 16 + 4 * tig);
                afr[mi][3] = *(const uint32_t*)(sa + r8 + kk + 16 + 4 * tig);
            }
            #pragma unroll
            for (int ni = 0; ni < 4; ni++) {
                int c0 = (wn * 32 + ni * 8 + g) * SROW;
                bfr[ni][0] = *(const uint32_t*)(sb + c0 + kk + 4 * tig);
                bfr[ni][1] = *(const uint32_t*)(sb + c0 + kk + 16 + 4 * tig);
            }
            #pragma unroll
            for (int mi = 0; mi < 4; mi++)
                #pragma unroll
                for (int ni = 0; ni < 4; ni++) {
                    asm volatile(
                        "mma.sync.aligned.m16n8k32.row.col.s32.s8.s8.s32 "
                        "{%0,%1,%2,%3}, {%4,%5,%6,%7}, {%8,%9}, {%0,%1,%2,%3};"
                        : "+r"(acc[mi][ni][0]), "+r"(acc[mi][ni][1]),
                          "+r"(acc[mi][ni][2]), "+r"(acc[mi][ni][3])
                        : "r"(afr[mi][0]), "r"(afr[mi][1]), "r"(afr[mi][2]), "r"(afr[mi][3]),
                          "r"(bfr[ni][0]), "r"(bfr[ni][1]));
                }
        }
        __syncthreads();
    }

    #pragma unroll
    for (int mi = 0; mi < 4; mi++) {
        int m0 = bm * 128 + wm * 64 + mi * 16 + g;
        float s0 = g_srow[m0], s1 = g_srow[m0 + 8];
        #pragma unroll
        for (int ni = 0; ni < 4; ni++) {
            int n0 = bn * 128 + wn * 32 + ni * 8 + tig * 2;
            float w0 = ws[n0], w1 = ws[n0 + 1];
            size_t i00 = (size_t)m0 * N_DIM + n0;
            size_t i10 = (size_t)(m0 + 8) * N_DIM + n0;
            out[i00]     += (float)acc[mi][ni][0] * s0 * w0;
            out[i00 + 1] += (float)acc[mi][ni][1] * s0 * w1;
            out[i10]     += (float)acc[mi][ni][2] * s1 * w0;
            out[i10 + 1] += (float)acc[mi][ni][3] * s1 * w1;
        }
    }
}

// ---------------- launch (order-independent input dispatch) ----------------
extern "C" void kernel_launch(void* const* d_in, const int* in_sizes, int n_in,
                              void* d_out, int out_size)
{
    const float* x     = nullptr;
    const void*  wraw  = nullptr;
    const float* fpw   = nullptr;
    const int*   i_idx = nullptr;
    const int*   f_idx = nullptr;
    const float* c8k[3] = {nullptr, nullptr, nullptr};
    int nc = 0;

    for (int i = 0; i < n_in; i++) {
        long s = in_sizes[i];
        if      (s == (long)M_DIM * K_DIM)   x     = (const float*)d_in[i];
        else if (s == (long)N_DIM * INTN)    wraw  = d_in[i];
        else if (s == (long)N_DIM * FPN)     fpw   = (const float*)d_in[i];
        else if (s == INTN)                  i_idx = (const int*)d_in[i];
        else if (s == FPN)                   f_idx = (const int*)d_in[i];
        else if (s == N_DIM && nc < 3)       c8k[nc++] = (const float*)d_in[i];
    }
    float* out = (float*)d_out;

    detect_w_kernel<<<1, 256>>>(wraw);
    {
        size_t total = (size_t)N_DIM * INTN;
        int blocks = (int)((total / 16 + 255) / 256);
        repack_w_kernel<<<blocks, 256>>>(wraw);
    }
    classify_kernel<<<1, 256>>>(c8k[0], c8k[1], c8k[2]);
    quant_kernel<<<M_DIM, 256>>>(x, i_idx, f_idx);
    fp_gemm_kernel<<<dim3(N_DIM / 128, M_DIM / 128), 256>>>(fpw, out);
    int_gemm_kernel<<<dim3(N_DIM / 128, M_DIM / 128), 256>>>(out);
}

// round 5
// speedup vs baseline: 1.0603x; 1.0603x over previous
#include <cuda_runtime.h>
#include <cuda_bf16.h>
#include <cstdint>

#define M_DIM 512
#define K_DIM 8192
#define N_DIM 8192
#define FPN   256
#define INTN  7936   // = 124 * 64

// ---------------- scratch (no allocations allowed) ----------------
__device__ __align__(128) int8_t g_qs[(size_t)M_DIM * INTN]; // quantized activations (q_s)
__device__ __align__(128) int8_t g_w8[(size_t)N_DIM * INTN]; // repacked int8 weights (65 MB)
__device__ __align__(128) float  g_fpx[M_DIM * FPN];         // gathered fp activations
__device__ float  g_srow[M_DIM];                             // per-row scale
__device__ float  g_off[M_DIM];                              // row_min + 8*scale

// resolved pointers / modes
__device__ const float* g_p_bias;
__device__ const float* g_p_ws;
__device__ const float* g_p_rw;
__device__ int          g_wmode;   // 0 = int8 passthrough, 1 = int32, 2 = bf16
__device__ const int8_t* g_p_w8;   // B pointer used by the GEMM

// ---------------- PTX helpers ----------------
__device__ __forceinline__ uint32_t smem_u32(const void* p) {
    return (uint32_t)__cvta_generic_to_shared(p);
}
__device__ __forceinline__ void cp_async16(void* smem_ptr, const void* gmem_ptr) {
    asm volatile("cp.async.cg.shared.global [%0], [%1], 16;\n"
                 :: "r"(smem_u32(smem_ptr)), "l"(gmem_ptr));
}
#define CP_COMMIT() asm volatile("cp.async.commit_group;\n" ::)
#define CP_WAIT(N)  asm volatile("cp.async.wait_group %0;\n" :: "n"(N))

// ---------------- K-1: detect w_int's real dtype ----------------
__global__ void detect_w_kernel(const void* wraw)
{
    __shared__ int s_i32_bad, s_bf16_bad;
    if (threadIdx.x == 0) { s_i32_bad = 0; s_bf16_bad = 0; }
    __syncthreads();
    const int32_t* wi = (const int32_t*)wraw;
    for (int i = threadIdx.x; i < 4096; i += 256) {
        int32_t v = wi[i];
        if (v < -8 || v > 7) s_i32_bad = 1;
    }
    const __nv_bfloat16* wb = (const __nv_bfloat16*)wraw;
    for (int i = threadIdx.x; i < 4096; i += 256) {
        float f = __bfloat162float(wb[i]);
        if (!(f >= -8.0f && f <= 7.0f) || f != rintf(f)) s_bf16_bad = 1;
    }
    __syncthreads();
    if (threadIdx.x == 0) {
        if (!s_i32_bad)       { g_wmode = 1; g_p_w8 = g_w8; }
        else if (!s_bf16_bad) { g_wmode = 2; g_p_w8 = g_w8; }
        else                  { g_wmode = 0; g_p_w8 = (const int8_t*)wraw; }
    }
}

// ---------------- K-2: repack weights to int8 if needed ----------------
__global__ __launch_bounds__(256) void repack_w_kernel(const void* wraw)
{
    const int mode = g_wmode;
    if (mode == 0) return;
    const size_t total = (size_t)N_DIM * INTN;
    const size_t idx0 = ((size_t)blockIdx.x * 256 + threadIdx.x) * 16;
    if (idx0 >= total) return;
    int8_t outv[16];
    if (mode == 1) {
        const int4* wi = (const int4*)wraw;
        #pragma unroll
        for (int j = 0; j < 4; j++) {
            int4 v = wi[idx0 / 4 + j];
            outv[j * 4 + 0] = (int8_t)v.x; outv[j * 4 + 1] = (int8_t)v.y;
            outv[j * 4 + 2] = (int8_t)v.z; outv[j * 4 + 3] = (int8_t)v.w;
        }
    } else {
        const __nv_bfloat16* wb = (const __nv_bfloat16*)wraw;
        #pragma unroll
        for (int j = 0; j < 16; j++)
            outv[j] = (int8_t)(int)__bfloat162float(wb[idx0 + j]);
    }
    *(int4*)(g_w8 + idx0) = *(int4*)outv;
}

// ---------------- K0: classify the three 8192-float arrays ----------------
__global__ void classify_kernel(const float* c0, const float* c1, const float* c2)
{
    const float* cand[3] = {c0, c1, c2};
    __shared__ float red[64];
    __shared__ float mins[3], maxs[3];
    for (int a = 0; a < 3; a++) {
        float mn = 3.4e38f, mx = -3.4e38f;
        for (int i = threadIdx.x; i < 8192; i += 256) {
            float v = cand[a][i];
            mn = fminf(mn, v); mx = fmaxf(mx, v);
        }
        #pragma unroll
        for (int o = 16; o > 0; o >>= 1) {
            mn = fminf(mn, __shfl_xor_sync(0xFFFFFFFFu, mn, o));
            mx = fmaxf(mx, __shfl_xor_sync(0xFFFFFFFFu, mx, o));
        }
        int wid = threadIdx.x >> 5;
        if ((threadIdx.x & 31) == 0) { red[wid] = mn; red[32 + wid] = mx; }
        __syncthreads();
        if (threadIdx.x == 0) {
            float m1 = red[0], m2 = red[32];
            #pragma unroll
            for (int i = 1; i < 8; i++) { m1 = fminf(m1, red[i]); m2 = fmaxf(m2, red[32 + i]); }
            mins[a] = m1; maxs[a] = m2;
        }
        __syncthreads();
    }
    if (threadIdx.x == 0) {
        int iws = -1, ibias = -1, irw = -1;
        for (int a = 0; a < 3; a++) if (mins[a] > 0.0f) iws = a;
        for (int a = 0; a < 3; a++) {
            if (a == iws) continue;
            float amax = fmaxf(fabsf(mins[a]), fabsf(maxs[a]));
            if (amax < 0.1f) ibias = a;
        }
        for (int a = 0; a < 3; a++) if (a != iws && a != ibias) irw = a;
        g_p_ws = cand[iws]; g_p_bias = cand[ibias]; g_p_rw = cand[irw];
    }
}

// ---------------- K1: quantization — coalesced row load, smem gather ----------------
__global__ __launch_bounds__(256) void quant_kernel(
    const float* __restrict__ x,
    const int*   __restrict__ int_idx,
    const int*   __restrict__ fp_idx)
{
    __shared__ float s_x[K_DIM];    // full 32KB row, coalesced
    __shared__ float s_red[80];
    const int m = blockIdx.x;
    const float* xrow = x + (size_t)m * K_DIM;

    // coalesced float4 load of the whole row
    const float4* x4 = (const float4*)xrow;
    #pragma unroll
    for (int j = 0; j < K_DIM / 4 / 256; j++)
        ((float4*)s_x)[j * 256 + threadIdx.x] = x4[j * 256 + threadIdx.x];
    __syncthreads();

    float lmin = 3.4e38f, lmax = -3.4e38f;
    for (int k = threadIdx.x; k < INTN; k += 256) {
        float v = s_x[int_idx[k]];
        lmin = fminf(lmin, v);
        lmax = fmaxf(lmax, v);
    }
    #pragma unroll
    for (int o = 16; o > 0; o >>= 1) {
        lmin = fminf(lmin, __shfl_xor_sync(0xFFFFFFFFu, lmin, o));
        lmax = fmaxf(lmax, __shfl_xor_sync(0xFFFFFFFFu, lmax, o));
    }
    const int wid = threadIdx.x >> 5;
    if ((threadIdx.x & 31) == 0) { s_red[wid] = lmin; s_red[32 + wid] = lmax; }
    __syncthreads();
    if (threadIdx.x == 0) {
        float mn = s_red[0], mx = s_red[32];
        #pragma unroll
        for (int i = 1; i < 8; i++) { mn = fminf(mn, s_red[i]); mx = fmaxf(mx, s_red[32 + i]); }
        float sc = (mx - mn) / 15.0f;
        s_red[64] = mn; s_red[65] = sc;
        g_srow[m] = sc;
        g_off[m]  = mn + 8.0f * sc;
    }
    __syncthreads();
    const float mn = s_red[64], sc = s_red[65];
    for (int k = threadIdx.x; k < INTN; k += 256) {
        float q = rintf((s_x[int_idx[k]] - mn) / sc);   // half-to-even, matches jnp.round
        q = fminf(fmaxf(q, 0.0f), 15.0f);
        g_qs[(size_t)m * INTN + k] = (int8_t)((int)q - 8);
    }
    for (int k = threadIdx.x; k < FPN; k += 256)
        g_fpx[m * FPN + k] = s_x[fp_idx[k]];
}

// ---------------- K2: fp path (tf32 mma, cp.async double buffer) ----------------
// out[m][n] = fp_x[m,:].fp_w[n,:] + bias[n] + off[m]*reduced_w[n]
// f32 fed raw to tf32 mma (hw truncation) — error << 1e-3 threshold.
#define FROW 20   // padded floats per smem row (80B, 16B-aligned)
__global__ __launch_bounds__(256) void fp_gemm_kernel(
    const float* __restrict__ fpw, float* __restrict__ out)
{
    __shared__ float s_a[2][128 * FROW];
    __shared__ float s_b[2][128 * FROW];
    const float* __restrict__ bias = g_p_bias;
    const float* __restrict__ rw   = g_p_rw;
    const int bm = blockIdx.y, bn = blockIdx.x;
    const int tid = threadIdx.x;
    const int wid = tid >> 5, lane = tid & 31;
    const int wm = wid & 1, wn = wid >> 1;   // warp tile: 64 x 32
    const int g = lane >> 2, tig = lane & 3;

    float acc[4][4][4];
    #pragma unroll
    for (int a = 0; a < 4; a++)
        #pragma unroll
        for (int b = 0; b < 4; b++)
            #pragma unroll
            for (int c = 0; c < 4; c++) acc[a][b][c] = 0.0f;

    const int KT = FPN / 16;   // 16

    auto load_stage = [&](int st, int kt) {
        const int k0 = kt * 16;
        #pragma unroll
        for (int j = 0; j < 2; j++) {
            int i = tid + j * 256;          // 512 chunks: 128 rows x 4 x 16B
            int r = i >> 2, c4 = (i & 3) * 4;
            cp_async16(&s_a[st][r * FROW + c4],
                       g_fpx + (size_t)(bm * 128 + r) * FPN + k0 + c4);
        }
        #pragma unroll
        for (int j = 0; j < 2; j++) {
            int i = tid + j * 256;
            int r = i >> 2, c4 = (i & 3) * 4;
            cp_async16(&s_b[st][r * FROW + c4],
                       fpw + (size_t)(bn * 128 + r) * FPN + k0 + c4);
        }
    };

    load_stage(0, 0); CP_COMMIT();

    for (int kt = 0; kt < KT; kt++) {
        if (kt + 1 < KT) { load_stage((kt + 1) & 1, kt + 1); CP_COMMIT(); CP_WAIT(1); }
        else             { CP_WAIT(0); }
        __syncthreads();
        const float* sa = s_a[kt & 1];
        const float* sb = s_b[kt & 1];
        #pragma unroll
        for (int kk = 0; kk < 16; kk += 8) {
            uint32_t afr[4][4], bfr[4][2];
            #pragma unroll
            for (int mi = 0; mi < 4; mi++) {
                int r0 = (wm * 64 + mi * 16 + g) * FROW;
                int r8 = r0 + 8 * FROW;
                afr[mi][0] = __float_as_uint(sa[r0 + kk + tig]);
                afr[mi][1] = __float_as_uint(sa[r8 + kk + tig]);
                afr[mi][2] = __float_as_uint(sa[r0 + kk + tig + 4]);
                afr[mi][3] = __float_as_uint(sa[r8 + kk + tig + 4]);
            }
            #pragma unroll
            for (int ni = 0; ni < 4; ni++) {
                int c0 = (wn * 32 + ni * 8 + g) * FROW;
                bfr[ni][0] = __float_as_uint(sb[c0 + kk + tig]);
                bfr[ni][1] = __float_as_uint(sb[c0 + kk + tig + 4]);
            }
            #pragma unroll
            for (int mi = 0; mi < 4; mi++)
                #pragma unroll
                for (int ni = 0; ni < 4; ni++) {
                    asm volatile(
                        "mma.sync.aligned.m16n8k8.row.col.f32.tf32.tf32.f32 "
                        "{%0,%1,%2,%3}, {%4,%5,%6,%7}, {%8,%9}, {%0,%1,%2,%3};"
                        : "+f"(acc[mi][ni][0]), "+f"(acc[mi][ni][1]),
                          "+f"(acc[mi][ni][2]), "+f"(acc[mi][ni][3])
                        : "r"(afr[mi][0]), "r"(afr[mi][1]), "r"(afr[mi][2]), "r"(afr[mi][3]),
                          "r"(bfr[ni][0]), "r"(bfr[ni][1]));
                }
        }
        __syncthreads();
    }

    #pragma unroll
    for (int mi = 0; mi < 4; mi++) {
        int m0 = bm * 128 + wm * 64 + mi * 16 + g;
        float off0 = g_off[m0], off1 = g_off[m0 + 8];
        #pragma unroll
        for (int ni = 0; ni < 4; ni++) {
            int n0 = bn * 128 + wn * 32 + ni * 8 + tig * 2;
            float b0 = bias[n0], b1 = bias[n0 + 1];
            float r0 = rw[n0],   r1 = rw[n0 + 1];
            out[(size_t)m0 * N_DIM + n0]           = acc[mi][ni][0] + b0 + off0 * r0;
            out[(size_t)m0 * N_DIM + n0 + 1]       = acc[mi][ni][1] + b1 + off0 * r1;
            out[(size_t)(m0 + 8) * N_DIM + n0]     = acc[mi][ni][2] + b0 + off1 * r0;
            out[(size_t)(m0 + 8) * N_DIM + n0 + 1] = acc[mi][ni][3] + b1 + off1 * r1;
        }
    }
}

// ---------------- K3: int8 GEMM, 4-stage cp.async ring, out += acc*srow*ws -------
#define SROW   80                    // padded bytes per smem row
#define ISTAGE (128 * SROW)          // 10240 B per matrix per stage
#define IKT    (INTN / 64)           // 124 K-chunks of 64 bytes
#define ISMEM  (4 * 2 * ISTAGE)      // 81920 B dynamic smem

__global__ __launch_bounds__(256, 2) void int_gemm_kernel(float* __restrict__ out)
{
    extern __shared__ int8_t smem[];
    int8_t* s_a = smem;                  // [4][ISTAGE]
    int8_t* s_b = smem + 4 * ISTAGE;     // [4][ISTAGE]
    const int8_t* __restrict__ w  = g_p_w8;
    const float*  __restrict__ ws = g_p_ws;
    const int bm = blockIdx.y, bn = blockIdx.x;
    const int tid = threadIdx.x;
    const int wid = tid >> 5, lane = tid & 31;
    const int wm = wid & 1, wn = wid >> 1;
    const int g = lane >> 2, tig = lane & 3;

    int acc[4][4][4];
    #pragma unroll
    for (int a = 0; a < 4; a++)
        #pragma unroll
        for (int b = 0; b < 4; b++)
            #pragma unroll
            for (int c = 0; c < 4; c++) acc[a][b][c] = 0;

    auto load_stage = [&](int st, int kt) {
        const int k0 = kt * 64;
        #pragma unroll
        for (int j = 0; j < 2; j++) {
            int i = tid + j * 256;           // 512 chunks: 128 rows x 4 x 16B
            int r = i >> 2, cs = (i & 3) * 16;
            cp_async16(s_a + st * ISTAGE + r * SROW + cs,
                       g_qs + (size_t)(bm * 128 + r) * INTN + k0 + cs);
        }
        #pragma unroll
        for (int j = 0; j < 2; j++) {
            int i = tid + j * 256;
            int r = i >> 2, cs = (i & 3) * 16;
            cp_async16(s_b + st * ISTAGE + r * SROW + cs,
                       w + (size_t)(bn * 128 + r) * INTN + k0 + cs);
        }
    };

    load_stage(0, 0); CP_COMMIT();
    load_stage(1, 1); CP_COMMIT();
    load_stage(2, 2); CP_COMMIT();

    for (int kt = 0; kt < IKT; kt++) {
        CP_WAIT(2);
        __syncthreads();
        const int pf = kt + 3;
        if (pf < IKT) load_stage(pf & 3, pf);
        CP_COMMIT();                        // possibly-empty group keeps the count in step

        const int8_t* sa = s_a + (kt & 3) * ISTAGE;
        const int8_t* sb = s_b + (kt & 3) * ISTAGE;
        #pragma unroll
        for (int kk = 0; kk < 64; kk += 32) {
            uint32_t afr[4][4], bfr[4][2];
            #pragma unroll
            for (int mi = 0; mi < 4; mi++) {
                int r0 = (wm * 64 + mi * 16 + g) * SROW;
                int r8 = r0 + 8 * SROW;
                afr[mi][0] = *(const uint32_t*)(sa + r0 + kk + 4 * tig);
                afr[mi][1] = *(const uint32_t*)(sa + r8 + kk + 4 * tig);
                afr[mi][2] = *(const uint32_t*)(sa + r0 + kk + 16 + 4 * tig);
                afr[mi][3] = *(const uint32_t*)(sa + r8 + kk + 16 + 4 * tig);
            }
            #pragma unroll
            for (int ni = 0; ni < 4; ni++) {
                int c0 = (wn * 32 + ni * 8 + g) * SROW;
                bfr[ni][0] = *(const uint32_t*)(sb + c0 + kk + 4 * tig);
                bfr[ni][1] = *(const uint32_t*)(sb + c0 + kk + 16 + 4 * tig);
            }
            #pragma unroll
            for (int mi = 0; mi < 4; mi++)
                #pragma unroll
                for (int ni = 0; ni < 4; ni++) {
                    asm volatile(
                        "mma.sync.aligned.m16n8k32.row.col.s32.s8.s8.s32 "
                        "{%0,%1,%2,%3}, {%4,%5,%6,%7}, {%8,%9}, {%0,%1,%2,%3};"
                        : "+r"(acc[mi][ni][0]), "+r"(acc[mi][ni][1]),
                          "+r"(acc[mi][ni][2]), "+r"(acc[mi][ni][3])
                        : "r"(afr[mi][0]), "r"(afr[mi][1]), "r"(afr[mi][2]), "r"(afr[mi][3]),
                          "r"(bfr[ni][0]), "r"(bfr[ni][1]));
                }
        }
    }

    #pragma unroll
    for (int mi = 0; mi < 4; mi++) {
        int m0 = bm * 128 + wm * 64 + mi * 16 + g;
        float s0 = g_srow[m0], s1 = g_srow[m0 + 8];
        #pragma unroll
        for (int ni = 0; ni < 4; ni++) {
            int n0 = bn * 128 + wn * 32 + ni * 8 + tig * 2;
            float w0 = ws[n0], w1 = ws[n0 + 1];
            size_t i00 = (size_t)m0 * N_DIM + n0;
            size_t i10 = (size_t)(m0 + 8) * N_DIM + n0;
            out[i00]     += (float)acc[mi][ni][0] * s0 * w0;
            out[i00 + 1] += (float)acc[mi][ni][1] * s0 * w1;
            out[i10]     += (float)acc[mi][ni][2] * s1 * w0;
            out[i10 + 1] += (float)acc[mi][ni][3] * s1 * w1;
        }
    }
}

// ---------------- launch (order-independent input dispatch) ----------------
extern "C" void kernel_launch(void* const* d_in, const int* in_sizes, int n_in,
                              void* d_out, int out_size)
{
    const float* x     = nullptr;
    const void*  wraw  = nullptr;
    const float* fpw   = nullptr;
    const int*   i_idx = nullptr;
    const int*   f_idx = nullptr;
    const float* c8k[3] = {nullptr, nullptr, nullptr};
    int nc = 0;

    for (int i = 0; i < n_in; i++) {
        long s = in_sizes[i];
        if      (s == (long)M_DIM * K_DIM)   x     = (const float*)d_in[i];
        else if (s == (long)N_DIM * INTN)    wraw  = d_in[i];
        else if (s == (long)N_DIM * FPN)     fpw   = (const float*)d_in[i];
        else if (s == INTN)                  i_idx = (const int*)d_in[i];
        else if (s == FPN)                   f_idx = (const int*)d_in[i];
        else if (s == N_DIM && nc < 3)       c8k[nc++] = (const float*)d_in[i];
    }
    float* out = (float*)d_out;

    static int smem_set = 0;
    if (!smem_set) {
        cudaFuncSetAttribute(int_gemm_kernel,
                             cudaFuncAttributeMaxDynamicSharedMemorySize, ISMEM);
        smem_set = 1;
    }

    detect_w_kernel<<<1, 256>>>(wraw);
    {
        size_t total = (size_t)N_DIM * INTN;
        int blocks = (int)((total / 16 + 255) / 256);
        repack_w_kernel<<<blocks, 256>>>(wraw);
    }
    classify_kernel<<<1, 256>>>(c8k[0], c8k[1], c8k[2]);
    quant_kernel<<<M_DIM, 256>>>(x, i_idx, f_idx);
    fp_gemm_kernel<<<dim3(N_DIM / 128, M_DIM / 128), 256>>>(fpw, out);
    int_gemm_kernel<<<dim3(N_DIM / 128, M_DIM / 128), 256, ISMEM>>>(out);
}

// round 6
// speedup vs baseline: 1.1574x; 1.0916x over previous
#include <cuda_runtime.h>
#include <cuda_bf16.h>
#include <cstdint>

#define M_DIM 512
#define K_DIM 8192
#define N_DIM 8192
#define FPN   256
#define INTN  7936   // = 124 * 64

// ---------------- scratch (no allocations allowed) ----------------
__device__ __align__(128) int8_t g_qs[(size_t)M_DIM * INTN]; // quantized activations (q_s)
__device__ __align__(128) int8_t g_w8[(size_t)N_DIM * INTN]; // repacked int8 weights (65 MB)
__device__ __align__(128) float  g_fpx[M_DIM * FPN];         // gathered fp activations
__device__ float  g_srow[M_DIM];                             // per-row scale
__device__ float  g_off[M_DIM];                              // row_min + 8*scale

// resolved pointers / modes
__device__ const float* g_p_bias;
__device__ const float* g_p_ws;
__device__ const float* g_p_rw;
__device__ int          g_wmode;   // 0 = int8 passthrough, 1 = int32, 2 = bf16
__device__ const int8_t* g_p_w8;   // B pointer used by the GEMM

// ---------------- PTX helpers ----------------
__device__ __forceinline__ uint32_t smem_u32(const void* p) {
    return (uint32_t)__cvta_generic_to_shared(p);
}
__device__ __forceinline__ void cp_async16(void* smem_ptr, const void* gmem_ptr) {
    asm volatile("cp.async.cg.shared.global [%0], [%1], 16;\n"
                 :: "r"(smem_u32(smem_ptr)), "l"(gmem_ptr));
}
#define CP_COMMIT() asm volatile("cp.async.commit_group;\n" ::)
#define CP_WAIT(N)  asm volatile("cp.async.wait_group %0;\n" :: "n"(N))
#define LDSM_X4(r0, r1, r2, r3, addr) \
    asm volatile("ldmatrix.sync.aligned.m8n8.x4.shared.b16 {%0,%1,%2,%3}, [%4];" \
                 : "=r"(r0), "=r"(r1), "=r"(r2), "=r"(r3) : "r"(addr))

// ---------------- K-1: detect w_int's real dtype ----------------
__global__ void detect_w_kernel(const void* wraw)
{
    __shared__ int s_i32_bad, s_bf16_bad;
    if (threadIdx.x == 0) { s_i32_bad = 0; s_bf16_bad = 0; }
    __syncthreads();
    const int32_t* wi = (const int32_t*)wraw;
    for (int i = threadIdx.x; i < 4096; i += 256) {
        int32_t v = wi[i];
        if (v < -8 || v > 7) s_i32_bad = 1;
    }
    const __nv_bfloat16* wb = (const __nv_bfloat16*)wraw;
    for (int i = threadIdx.x; i < 4096; i += 256) {
        float f = __bfloat162float(wb[i]);
        if (!(f >= -8.0f && f <= 7.0f) || f != rintf(f)) s_bf16_bad = 1;
    }
    __syncthreads();
    if (threadIdx.x == 0) {
        if (!s_i32_bad)       { g_wmode = 1; g_p_w8 = g_w8; }
        else if (!s_bf16_bad) { g_wmode = 2; g_p_w8 = g_w8; }
        else                  { g_wmode = 0; g_p_w8 = (const int8_t*)wraw; }
    }
}

// ---------------- K-2: repack weights to int8 if needed ----------------
__global__ __launch_bounds__(256) void repack_w_kernel(const void* wraw)
{
    const int mode = g_wmode;
    if (mode == 0) return;
    const size_t total = (size_t)N_DIM * INTN;
    const size_t idx0 = ((size_t)blockIdx.x * 256 + threadIdx.x) * 16;
    if (idx0 >= total) return;
    int8_t outv[16];
    if (mode == 1) {
        const int4* wi = (const int4*)wraw;
        #pragma unroll
        for (int j = 0; j < 4; j++) {
            int4 v = wi[idx0 / 4 + j];
            outv[j * 4 + 0] = (int8_t)v.x; outv[j * 4 + 1] = (int8_t)v.y;
            outv[j * 4 + 2] = (int8_t)v.z; outv[j * 4 + 3] = (int8_t)v.w;
        }
    } else {
        const __nv_bfloat16* wb = (const __nv_bfloat16*)wraw;
        #pragma unroll
        for (int j = 0; j < 16; j++)
            outv[j] = (int8_t)(int)__bfloat162float(wb[idx0 + j]);
    }
    *(int4*)(g_w8 + idx0) = *(int4*)outv;
}

// ---------------- K0: classify the three 8192-float arrays ----------------
__global__ void classify_kernel(const float* c0, const float* c1, const float* c2)
{
    const float* cand[3] = {c0, c1, c2};
    __shared__ float red[64];
    __shared__ float mins[3], maxs[3];
    for (int a = 0; a < 3; a++) {
        float mn = 3.4e38f, mx = -3.4e38f;
        for (int i = threadIdx.x; i < 8192; i += 256) {
            float v = cand[a][i];
            mn = fminf(mn, v); mx = fmaxf(mx, v);
        }
        #pragma unroll
        for (int o = 16; o > 0; o >>= 1) {
            mn = fminf(mn, __shfl_xor_sync(0xFFFFFFFFu, mn, o));
            mx = fmaxf(mx, __shfl_xor_sync(0xFFFFFFFFu, mx, o));
        }
        int wid = threadIdx.x >> 5;
        if ((threadIdx.x & 31) == 0) { red[wid] = mn; red[32 + wid] = mx; }
        __syncthreads();
        if (threadIdx.x == 0) {
            float m1 = red[0], m2 = red[32];
            #pragma unroll
            for (int i = 1; i < 8; i++) { m1 = fminf(m1, red[i]); m2 = fmaxf(m2, red[32 + i]); }
            mins[a] = m1; maxs[a] = m2;
        }
        __syncthreads();
    }
    if (threadIdx.x == 0) {
        int iws = -1, ibias = -1, irw = -1;
        for (int a = 0; a < 3; a++) if (mins[a] > 0.0f) iws = a;
        for (int a = 0; a < 3; a++) {
            if (a == iws) continue;
            float amax = fmaxf(fabsf(mins[a]), fabsf(maxs[a]));
            if (amax < 0.1f) ibias = a;
        }
        for (int a = 0; a < 3; a++) if (a != iws && a != ibias) irw = a;
        g_p_ws = cand[iws]; g_p_bias = cand[ibias]; g_p_rw = cand[irw];
    }
}

// ---------------- K1: quantization — coalesced row load, smem gather ----------------
__global__ __launch_bounds__(256) void quant_kernel(
    const float* __restrict__ x,
    const int*   __restrict__ int_idx,
    const int*   __restrict__ fp_idx)
{
    __shared__ float s_x[K_DIM];    // full 32KB row, coalesced
    __shared__ float s_red[80];
    const int m = blockIdx.x;
    const float* xrow = x + (size_t)m * K_DIM;

    const float4* x4 = (const float4*)xrow;
    #pragma unroll
    for (int j = 0; j < K_DIM / 4 / 256; j++)
        ((float4*)s_x)[j * 256 + threadIdx.x] = x4[j * 256 + threadIdx.x];
    __syncthreads();

    float lmin = 3.4e38f, lmax = -3.4e38f;
    for (int k = threadIdx.x; k < INTN; k += 256) {
        float v = s_x[int_idx[k]];
        lmin = fminf(lmin, v);
        lmax = fmaxf(lmax, v);
    }
    #pragma unroll
    for (int o = 16; o > 0; o >>= 1) {
        lmin = fminf(lmin, __shfl_xor_sync(0xFFFFFFFFu, lmin, o));
        lmax = fmaxf(lmax, __shfl_xor_sync(0xFFFFFFFFu, lmax, o));
    }
    const int wid = threadIdx.x >> 5;
    if ((threadIdx.x & 31) == 0) { s_red[wid] = lmin; s_red[32 + wid] = lmax; }
    __syncthreads();
    if (threadIdx.x == 0) {
        float mn = s_red[0], mx = s_red[32];
        #pragma unroll
        for (int i = 1; i < 8; i++) { mn = fminf(mn, s_red[i]); mx = fmaxf(mx, s_red[32 + i]); }
        float sc = (mx - mn) / 15.0f;
        s_red[64] = mn; s_red[65] = sc;
        g_srow[m] = sc;
        g_off[m]  = mn + 8.0f * sc;
    }
    __syncthreads();
    const float mn = s_red[64], sc = s_red[65];
    for (int k = threadIdx.x; k < INTN; k += 256) {
        float q = rintf((s_x[int_idx[k]] - mn) / sc);   // half-to-even, matches jnp.round
        q = fminf(fmaxf(q, 0.0f), 15.0f);
        g_qs[(size_t)m * INTN + k] = (int8_t)((int)q - 8);
    }
    for (int k = threadIdx.x; k < FPN; k += 256)
        g_fpx[m * FPN + k] = s_x[fp_idx[k]];
}

// ---------------- K2: fp path (tf32 mma, cp.async double buffer) ----------------
#define FROW 20   // padded floats per smem row (80B, 16B-aligned)
__global__ __launch_bounds__(256) void fp_gemm_kernel(
    const float* __restrict__ fpw, float* __restrict__ out)
{
    __shared__ float s_a[2][128 * FROW];
    __shared__ float s_b[2][128 * FROW];
    const float* __restrict__ bias = g_p_bias;
    const float* __restrict__ rw   = g_p_rw;
    const int bm = blockIdx.y, bn = blockIdx.x;
    const int tid = threadIdx.x;
    const int wid = tid >> 5, lane = tid & 31;
    const int wm = wid & 1, wn = wid >> 1;
    const int g = lane >> 2, tig = lane & 3;

    float acc[4][4][4];
    #pragma unroll
    for (int a = 0; a < 4; a++)
        #pragma unroll
        for (int b = 0; b < 4; b++)
            #pragma unroll
            for (int c = 0; c < 4; c++) acc[a][b][c] = 0.0f;

    const int KT = FPN / 16;

    auto load_stage = [&](int st, int kt) {
        const int k0 = kt * 16;
        #pragma unroll
        for (int j = 0; j < 2; j++) {
            int i = tid + j * 256;
            int r = i >> 2, c4 = (i & 3) * 4;
            cp_async16(&s_a[st][r * FROW + c4],
                       g_fpx + (size_t)(bm * 128 + r) * FPN + k0 + c4);
        }
        #pragma unroll
        for (int j = 0; j < 2; j++) {
            int i = tid + j * 256;
            int r = i >> 2, c4 = (i & 3) * 4;
            cp_async16(&s_b[st][r * FROW + c4],
                       fpw + (size_t)(bn * 128 + r) * FPN + k0 + c4);
        }
    };

    load_stage(0, 0); CP_COMMIT();

    for (int kt = 0; kt < KT; kt++) {
        if (kt + 1 < KT) { load_stage((kt + 1) & 1, kt + 1); CP_COMMIT(); CP_WAIT(1); }
        else             { CP_WAIT(0); }
        __syncthreads();
        const float* sa = s_a[kt & 1];
        const float* sb = s_b[kt & 1];
        #pragma unroll
        for (int kk = 0; kk < 16; kk += 8) {
            uint32_t afr[4][4], bfr[4][2];
            #pragma unroll
            for (int mi = 0; mi < 4; mi++) {
                int r0 = (wm * 64 + mi * 16 + g) * FROW;
                int r8 = r0 + 8 * FROW;
                afr[mi][0] = __float_as_uint(sa[r0 + kk + tig]);
                afr[mi][1] = __float_as_uint(sa[r8 + kk + tig]);
                afr[mi][2] = __float_as_uint(sa[r0 + kk + tig + 4]);
                afr[mi][3] = __float_as_uint(sa[r8 + kk + tig + 4]);
            }
            #pragma unroll
            for (int ni = 0; ni < 4; ni++) {
                int c0 = (wn * 32 + ni * 8 + g) * FROW;
                bfr[ni][0] = __float_as_uint(sb[c0 + kk + tig]);
                bfr[ni][1] = __float_as_uint(sb[c0 + kk + tig + 4]);
            }
            #pragma unroll
            for (int mi = 0; mi < 4; mi++)
                #pragma unroll
                for (int ni = 0; ni < 4; ni++) {
                    asm volatile(
                        "mma.sync.aligned.m16n8k8.row.col.f32.tf32.tf32.f32 "
                        "{%0,%1,%2,%3}, {%4,%5,%6,%7}, {%8,%9}, {%0,%1,%2,%3};"
                        : "+f"(acc[mi][ni][0]), "+f"(acc[mi][ni][1]),
                          "+f"(acc[mi][ni][2]), "+f"(acc[mi][ni][3])
                        : "r"(afr[mi][0]), "r"(afr[mi][1]), "r"(afr[mi][2]), "r"(afr[mi][3]),
                          "r"(bfr[ni][0]), "r"(bfr[ni][1]));
                }
        }
        __syncthreads();
    }

    #pragma unroll
    for (int mi = 0; mi < 4; mi++) {
        int m0 = bm * 128 + wm * 64 + mi * 16 + g;
        float off0 = g_off[m0], off1 = g_off[m0 + 8];
        #pragma unroll
        for (int ni = 0; ni < 4; ni++) {
            int n0 = bn * 128 + wn * 32 + ni * 8 + tig * 2;
            float b0 = bias[n0], b1 = bias[n0 + 1];
            float r0 = rw[n0],   r1 = rw[n0 + 1];
            out[(size_t)m0 * N_DIM + n0]           = acc[mi][ni][0] + b0 + off0 * r0;
            out[(size_t)m0 * N_DIM + n0 + 1]       = acc[mi][ni][1] + b1 + off0 * r1;
            out[(size_t)(m0 + 8) * N_DIM + n0]     = acc[mi][ni][2] + b0 + off1 * r0;
            out[(size_t)(m0 + 8) * N_DIM + n0 + 1] = acc[mi][ni][3] + b1 + off1 * r1;
        }
    }
}

// ---------------- K3: int8 GEMM, ldmatrix fragments, 4-stage ring ----------------
#define SROW   80                    // padded bytes per smem row
#define ISTAGE (128 * SROW)          // 10240 B per matrix per stage
#define IKT    (INTN / 64)           // 124 K-chunks of 64 bytes
#define ISMEM  (4 * 2 * ISTAGE)      // 81920 B dynamic smem

__global__ __launch_bounds__(256, 2) void int_gemm_kernel(float* __restrict__ out)
{
    extern __shared__ int8_t smem[];
    int8_t* s_a = smem;                  // [4][ISTAGE]
    int8_t* s_b = smem + 4 * ISTAGE;     // [4][ISTAGE]
    const uint32_t sa_u0 = smem_u32(s_a);
    const uint32_t sb_u0 = smem_u32(s_b);
    const int8_t* __restrict__ w  = g_p_w8;
    const float*  __restrict__ ws = g_p_ws;
    // L2-friendly order: 4 consecutive CTAs share the same B tile
    const int bm = blockIdx.x & 3, bn = blockIdx.x >> 2;
    const int tid = threadIdx.x;
    const int wid = tid >> 5, lane = tid & 31;
    const int wm = wid & 1, wn = wid >> 1;
    const int g = lane >> 2, tig = lane & 3;

    // ldmatrix lane offsets (bytes from stage base)
    // A (x4 -> rows r..r+15 x 32 cols): row = wm*64 + (lane&15), col16 = (lane>>4)*16
    const uint32_t aLaneOff = (uint32_t)((wm * 64 + (lane & 15)) * SROW + (lane >> 4) * 16);
    // B pair (x4 -> ni=2p rows 0-7 / ni=2p+1 rows 8-15, col16 = bit3 of lane)
    const uint32_t bLaneOff = (uint32_t)((wn * 32 + ((lane >> 4) & 1) * 8 + (lane & 7)) * SROW
                                         + ((lane >> 3) & 1) * 16);

    int acc[4][4][4];
    #pragma unroll
    for (int a = 0; a < 4; a++)
        #pragma unroll
        for (int b = 0; b < 4; b++)
            #pragma unroll
            for (int c = 0; c < 4; c++) acc[a][b][c] = 0;

    auto load_stage = [&](int st, int kt) {
        const int k0 = kt * 64;
        #pragma unroll
        for (int j = 0; j < 2; j++) {
            int i = tid + j * 256;           // 512 chunks: 128 rows x 4 x 16B
            int r = i >> 2, cs = (i & 3) * 16;
            cp_async16(s_a + st * ISTAGE + r * SROW + cs,
                       g_qs + (size_t)(bm * 128 + r) * INTN + k0 + cs);
        }
        #pragma unroll
        for (int j = 0; j < 2; j++) {
            int i = tid + j * 256;
            int r = i >> 2, cs = (i & 3) * 16;
            cp_async16(s_b + st * ISTAGE + r * SROW + cs,
                       w + (size_t)(bn * 128 + r) * INTN + k0 + cs);
        }
    };

    load_stage(0, 0); CP_COMMIT();
    load_stage(1, 1); CP_COMMIT();
    load_stage(2, 2); CP_COMMIT();

    for (int kt = 0; kt < IKT; kt++) {
        CP_WAIT(2);
        __syncthreads();
        const int pf = kt + 3;
        if (pf < IKT) load_stage(pf & 3, pf);
        CP_COMMIT();                        // possibly-empty group keeps the count in step

        const uint32_t aAddr = sa_u0 + (uint32_t)((kt & 3) * ISTAGE) + aLaneOff;
        const uint32_t bAddr = sb_u0 + (uint32_t)((kt & 3) * ISTAGE) + bLaneOff;
        #pragma unroll
        for (int kk = 0; kk < 64; kk += 32) {
            uint32_t afr[4][4], bfr[4][2];
            #pragma unroll
            for (int mi = 0; mi < 4; mi++)
                LDSM_X4(afr[mi][0], afr[mi][1], afr[mi][2], afr[mi][3],
                        aAddr + mi * 16 * SROW + kk);
            #pragma unroll
            for (int p = 0; p < 2; p++)
                LDSM_X4(bfr[2 * p][0], bfr[2 * p][1], bfr[2 * p + 1][0], bfr[2 * p + 1][1],
                        bAddr + p * 16 * SROW + kk);
            #pragma unroll
            for (int mi = 0; mi < 4; mi++)
                #pragma unroll
                for (int ni = 0; ni < 4; ni++) {
                    asm volatile(
                        "mma.sync.aligned.m16n8k32.row.col.s32.s8.s8.s32 "
                        "{%0,%1,%2,%3}, {%4,%5,%6,%7}, {%8,%9}, {%0,%1,%2,%3};"
                        : "+r"(acc[mi][ni][0]), "+r"(acc[mi][ni][1]),
                          "+r"(acc[mi][ni][2]), "+r"(acc[mi][ni][3])
                        : "r"(afr[mi][0]), "r"(afr[mi][1]), "r"(afr[mi][2]), "r"(afr[mi][3]),
                          "r"(bfr[ni][0]), "r"(bfr[ni][1]));
                }
        }
    }

    #pragma unroll
    for (int mi = 0; mi < 4; mi++) {
        int m0 = bm * 128 + wm * 64 + mi * 16 + g;
        float s0 = g_srow[m0], s1 = g_srow[m0 + 8];
        #pragma unroll
        for (int ni = 0; ni < 4; ni++) {
            int n0 = bn * 128 + wn * 32 + ni * 8 + tig * 2;
            float w0 = ws[n0], w1 = ws[n0 + 1];
            size_t i00 = (size_t)m0 * N_DIM + n0;
            size_t i10 = (size_t)(m0 + 8) * N_DIM + n0;
            out[i00]     += (float)acc[mi][ni][0] * s0 * w0;
            out[i00 + 1] += (float)acc[mi][ni][1] * s0 * w1;
            out[i10]     += (float)acc[mi][ni][2] * s1 * w0;
            out[i10 + 1] += (float)acc[mi][ni][3] * s1 * w1;
        }
    }
}

// ---------------- launch (order-independent input dispatch) ----------------
extern "C" void kernel_launch(void* const* d_in, const int* in_sizes, int n_in,
                              void* d_out, int out_size)
{
    const float* x     = nullptr;
    const void*  wraw  = nullptr;
    const float* fpw   = nullptr;
    const int*   i_idx = nullptr;
    const int*   f_idx = nullptr;
    const float* c8k[3] = {nullptr, nullptr, nullptr};
    int nc = 0;

    for (int i = 0; i < n_in; i++) {
        long s = in_sizes[i];
        if      (s == (long)M_DIM * K_DIM)   x     = (const float*)d_in[i];
        else if (s == (long)N_DIM * INTN)    wraw  = d_in[i];
        else if (s == (long)N_DIM * FPN)     fpw   = (const float*)d_in[i];
        else if (s == INTN)                  i_idx = (const int*)d_in[i];
        else if (s == FPN)                   f_idx = (const int*)d_in[i];
        else if (s == N_DIM && nc < 3)       c8k[nc++] = (const float*)d_in[i];
    }
    float* out = (float*)d_out;

    static int smem_set = 0;
    if (!smem_set) {
        cudaFuncSetAttribute(int_gemm_kernel,
                             cudaFuncAttributeMaxDynamicSharedMemorySize, ISMEM);
        smem_set = 1;
    }

    detect_w_kernel<<<1, 256>>>(wraw);
    {
        size_t total = (size_t)N_DIM * INTN;
        int blocks = (int)((total / 16 + 255) / 256);
        repack_w_kernel<<<blocks, 256>>>(wraw);
    }
    classify_kernel<<<1, 256>>>(c8k[0], c8k[1], c8k[2]);
    quant_kernel<<<M_DIM, 256>>>(x, i_idx, f_idx);
    fp_gemm_kernel<<<dim3(N_DIM / 128, M_DIM / 128), 256>>>(fpw, out);
    int_gemm_kernel<<<dim3(256, 1), 256, ISMEM>>>(out);
}